// round 12
// baseline (speedup 1.0000x reference)
#include <cuda_runtime.h>
#include <cuda_bf16.h>
#include <stdint.h>

// B=8, T=2048, D=768, QKV_OUT=2304. Single-head attention over full 768 dims,
// scale 1/sqrt(64)=0.125. All GEMMs NT mma.sync bf16 split hi/lo 3-pass.
// Operands pre-split into gmem bf16 hi/lo planes; GEMM = cp.async+ldmatrix+MMA.
#define BT 16384
#define DIM 768
#define QKVO 2304
#define SEQ 2048
#define NB 8
#define SCALE 0.125f

// fp32 scratch
__device__ float g_scores[(size_t)NB * SEQ * SEQ];   // 8 x 2048 x 2048
__device__ float g_v[(size_t)BT * DIM];              // V fp32 (pre-transpose)
// bf16 hi/lo planes
__device__ __nv_bfloat16 g_xh[(size_t)BT * DIM],  g_xl[(size_t)BT * DIM];
__device__ __nv_bfloat16 g_qh[(size_t)BT * DIM],  g_ql[(size_t)BT * DIM];
__device__ __nv_bfloat16 g_kh[(size_t)BT * DIM],  g_kl[(size_t)BT * DIM];
__device__ __nv_bfloat16 g_vth[(size_t)NB * DIM * SEQ], g_vtl[(size_t)NB * DIM * SEQ];
__device__ __nv_bfloat16 g_ph[(size_t)NB * SEQ * SEQ],  g_pl[(size_t)NB * SEQ * SEQ];
__device__ __nv_bfloat16 g_oh[(size_t)BT * DIM],  g_ol[(size_t)BT * DIM];
__device__ __nv_bfloat16 g_wqh[(size_t)QKVO * DIM], g_wql[(size_t)QKVO * DIM];
__device__ __nv_bfloat16 g_woh[(size_t)DIM * DIM],  g_wol[(size_t)DIM * DIM];

// split pair (x -> lower k, y -> upper k) into packed hi word + lo word
__device__ __forceinline__ void split2(float x, float y, uint32_t& h, uint32_t& l) {
    __nv_bfloat16 hx = __float2bfloat16(x), hy = __float2bfloat16(y);
    __nv_bfloat16 lx = __float2bfloat16(x - __bfloat162float(hx));
    __nv_bfloat16 ly = __float2bfloat16(y - __bfloat162float(hy));
    h = ((uint32_t)__bfloat16_as_ushort(hy) << 16) | (uint32_t)__bfloat16_as_ushort(hx);
    l = ((uint32_t)__bfloat16_as_ushort(ly) << 16) | (uint32_t)__bfloat16_as_ushort(lx);
}
__device__ __forceinline__ void mma_bf16(float* d, const uint32_t* a, const uint32_t* b) {
    asm volatile(
        "mma.sync.aligned.m16n8k16.row.col.f32.bf16.bf16.f32 "
        "{%0,%1,%2,%3}, {%4,%5,%6,%7}, {%8,%9}, {%0,%1,%2,%3};"
        : "+f"(d[0]), "+f"(d[1]), "+f"(d[2]), "+f"(d[3])
        : "r"(a[0]), "r"(a[1]), "r"(a[2]), "r"(a[3]), "r"(b[0]), "r"(b[1]));
}
#define LDSM_X4(r0, r1, r2, r3, addr) \
    asm volatile("ldmatrix.sync.aligned.m8n8.x4.shared.b16 {%0,%1,%2,%3}, [%4];" \
        : "=r"(r0), "=r"(r1), "=r"(r2), "=r"(r3) : "r"(addr))
#define CP16(dst, src) \
    asm volatile("cp.async.ca.shared.global [%0], [%1], 16;" :: "r"(dst), "l"(src))
#define CPCOMMIT() asm volatile("cp.async.commit_group;")
#define CPWAIT1() asm volatile("cp.async.wait_group 1;")
#define CPWAIT0() asm volatile("cp.async.wait_group 0;")

// Smem per buffer: Ah[128x80B] Al Bh Bl = 40960 B; two buffers.
#define BUFB 40960
#define GEMM_SMEM (2 * BUFB)

// ---------------------------------------------------------------------------
// NT GEMM on pre-split planes: C = alpha*A@B^T (+bias). BM=BN=128, BK=32.
// 512 thr = 16 warps (4M x 4N), warp tile 32x32. cp.async double buffer.
// OMODE 0: fp32 C (o0). OMODE 1: plane C (o0=hi, o1=lo).
// OMODE 2: qkv split -> Q planes (o0,o1), K planes (o2,o3), V fp32 (o4).
// ---------------------------------------------------------------------------
template<int OMODE>
__global__ __launch_bounds__(512)
void gemm_pl(const __nv_bfloat16* __restrict__ Ah, const __nv_bfloat16* __restrict__ Al,
             const __nv_bfloat16* __restrict__ Bh, const __nv_bfloat16* __restrict__ Bl,
             void* o0, void* o1, void* o2, void* o3, void* o4,
             const float* __restrict__ bias,
             int K, int lda, int ldb, int ldc, float alpha,
             long long sA, long long sB, long long sC)
{
    extern __shared__ __align__(16) char smem[];
    const int tid = threadIdx.x;
    const int lane = tid & 31, wid = tid >> 5;
    const int wm = (wid >> 2) * 32;     // 0/32/64/96
    const int wn = (wid & 3) * 32;
    const int lr = lane >> 2, lc = lane & 3;
    const uint32_t sbase = (uint32_t)__cvta_generic_to_shared(smem);
    const int lm_i = lane & 7, lm_j = lane >> 3;
    const uint32_t laneoff = (uint32_t)((lm_i + (lm_j & 1) * 8) * 80 + (lm_j >> 1) * 16);

    // loader: thread -> {surface A/B, plane hi/lo, row}; 64B (4x16B) per chunk
    const int l_surf = tid >> 8, l_plane = (tid >> 7) & 1, l_row = tid & 127;
    const __nv_bfloat16* lp;
    if (l_surf == 0)
        lp = (l_plane ? Al : Ah) + (size_t)blockIdx.z * sA
           + (size_t)(blockIdx.y * 128 + l_row) * lda;
    else
        lp = (l_plane ? Bl : Bh) + (size_t)blockIdx.z * sB
           + (size_t)(blockIdx.x * 128 + l_row) * ldb;
    const uint32_t l_dst0 = sbase
        + (uint32_t)(l_surf * 20480 + l_plane * 10240 + l_row * 80);

    float acc[2][4][4];
#pragma unroll
    for (int i = 0; i < 2; i++)
#pragma unroll
        for (int j = 0; j < 4; j++)
#pragma unroll
            for (int q = 0; q < 4; q++) acc[i][j][q] = 0.0f;

    const int nc = K >> 5;
    {   // prologue: chunk 0 -> buffer 0
        const __nv_bfloat16* s = lp;
        uint32_t d = l_dst0;
        CP16(d, s); CP16(d + 16, s + 8); CP16(d + 32, s + 16); CP16(d + 48, s + 24);
        CPCOMMIT();
    }

    for (int c = 0; c < nc; c++) {
        if (c + 1 < nc) {
            const __nv_bfloat16* s = lp + (c + 1) * 32;
            uint32_t d = l_dst0 + (uint32_t)(((c + 1) & 1) * BUFB);
            CP16(d, s); CP16(d + 16, s + 8); CP16(d + 32, s + 16); CP16(d + 48, s + 24);
            CPCOMMIT();
            CPWAIT1();
        } else {
            CPWAIT0();
        }
        __syncthreads();    // chunk c visible to all

        const uint32_t buf = sbase + (uint32_t)((c & 1) * BUFB);
#pragma unroll
        for (int ks = 0; ks < 2; ks++) {
            const uint32_t kb = (uint32_t)(ks * 32);
            uint32_t bh[4][2], bl[4][2];
#pragma unroll
            for (int q = 0; q < 2; q++) {
                uint32_t ba = buf + 20480 + (uint32_t)((wn + q * 16) * 80) + laneoff + kb;
                uint32_t r0, r1, r2, r3;
                LDSM_X4(r0, r1, r2, r3, ba);
                bh[q * 2][0] = r0; bh[q * 2 + 1][0] = r1;
                bh[q * 2][1] = r2; bh[q * 2 + 1][1] = r3;
                LDSM_X4(r0, r1, r2, r3, ba + 10240);
                bl[q * 2][0] = r0; bl[q * 2 + 1][0] = r1;
                bl[q * 2][1] = r2; bl[q * 2 + 1][1] = r3;
            }
#pragma unroll
            for (int im = 0; im < 2; im++) {
                uint32_t aa = buf + (uint32_t)((wm + im * 16) * 80) + laneoff + kb;
                uint32_t ah[4], al[4];
                LDSM_X4(ah[0], ah[1], ah[2], ah[3], aa);
                LDSM_X4(al[0], al[1], al[2], al[3], aa + 10240);
#pragma unroll
                for (int jn = 0; jn < 4; jn++) {
                    mma_bf16(acc[im][jn], ah, bh[jn]);   // hi*hi
                    mma_bf16(acc[im][jn], ah, bl[jn]);   // hi*lo
                    mma_bf16(acc[im][jn], al, bh[jn]);   // lo*hi
                }
            }
        }
        __syncthreads();    // all done reading buf[c&1] before it is refilled
    }

    // ---- epilogue ----
#pragma unroll
    for (int im = 0; im < 2; im++) {
        const int gr = blockIdx.y * 128 + wm + im * 16 + lr;
#pragma unroll
        for (int jn = 0; jn < 4; jn++) {
            const int ct = wn + jn * 8 + 2 * lc;      // col within 128-tile
            float v0 = alpha * acc[im][jn][0];
            float v1 = alpha * acc[im][jn][1];
            float v2 = alpha * acc[im][jn][2];
            float v3 = alpha * acc[im][jn][3];

            if (OMODE == 0) {
                const int gc = blockIdx.x * 128 + ct;
                if (bias) { v0 += bias[gc]; v1 += bias[gc + 1];
                            v2 += bias[gc]; v3 += bias[gc + 1]; }
                float* C = (float*)o0 + (size_t)blockIdx.z * sC;
                *(float2*)(C + (size_t)gr * ldc + gc) = make_float2(v0, v1);
                *(float2*)(C + (size_t)(gr + 8) * ldc + gc) = make_float2(v2, v3);
            } else if (OMODE == 1) {
                const int gc = blockIdx.x * 128 + ct;
                __nv_bfloat16* Ch = (__nv_bfloat16*)o0 + (size_t)blockIdx.z * sC;
                __nv_bfloat16* Cl = (__nv_bfloat16*)o1 + (size_t)blockIdx.z * sC;
                uint32_t h, l;
                split2(v0, v1, h, l);
                *(uint32_t*)((char*)Ch + ((size_t)gr * ldc + gc) * 2) = h;
                *(uint32_t*)((char*)Cl + ((size_t)gr * ldc + gc) * 2) = l;
                split2(v2, v3, h, l);
                *(uint32_t*)((char*)Ch + ((size_t)(gr + 8) * ldc + gc) * 2) = h;
                *(uint32_t*)((char*)Cl + ((size_t)(gr + 8) * ldc + gc) * 2) = l;
            } else {
                // QKV split: region from blockIdx.x (768 = 6 tiles of 128)
                const int reg = blockIdx.x / 6;
                const int gc = (blockIdx.x - reg * 6) * 128 + ct;   // col in region
                const int bcol = reg * 768 + gc;
                v0 += bias[bcol]; v1 += bias[bcol + 1];
                v2 += bias[bcol]; v3 += bias[bcol + 1];
                if (reg == 2) {
                    float* Vc = (float*)o4;
                    *(float2*)(Vc + (size_t)gr * 768 + gc) = make_float2(v0, v1);
                    *(float2*)(Vc + (size_t)(gr + 8) * 768 + gc) = make_float2(v2, v3);
                } else {
                    __nv_bfloat16* Ph = (__nv_bfloat16*)(reg == 0 ? o0 : o2);
                    __nv_bfloat16* Pl = (__nv_bfloat16*)(reg == 0 ? o1 : o3);
                    uint32_t h, l;
                    split2(v0, v1, h, l);
                    *(uint32_t*)((char*)Ph + ((size_t)gr * 768 + gc) * 2) = h;
                    *(uint32_t*)((char*)Pl + ((size_t)gr * 768 + gc) * 2) = l;
                    split2(v2, v3, h, l);
                    *(uint32_t*)((char*)Ph + ((size_t)(gr + 8) * 768 + gc) * 2) = h;
                    *(uint32_t*)((char*)Pl + ((size_t)(gr + 8) * 768 + gc) * 2) = l;
                }
            }
        }
    }
}

// ---------------------------------------------------------------------------
// Elementwise fp32 -> hi/lo planes. n4 = element count / 4.
// ---------------------------------------------------------------------------
__global__ __launch_bounds__(256)
void convert_pl(const float* __restrict__ src,
                __nv_bfloat16* __restrict__ dh, __nv_bfloat16* __restrict__ dl,
                int n4)
{
    int i = blockIdx.x * 256 + threadIdx.x;
    if (i < n4) {
        float4 v = ((const float4*)src)[i];
        uint32_t h0, l0, h1, l1;
        split2(v.x, v.y, h0, l0);
        split2(v.z, v.w, h1, l1);
        ((uint2*)dh)[i] = make_uint2(h0, h1);
        ((uint2*)dl)[i] = make_uint2(l0, l1);
    }
}

// ---------------------------------------------------------------------------
// Batched 32x32 transpose + split: dst planes[c][r] = split(src[r][c]).
// ---------------------------------------------------------------------------
__global__ __launch_bounds__(256)
void transpose_pl(const float* __restrict__ src,
                  __nv_bfloat16* __restrict__ dh, __nv_bfloat16* __restrict__ dl,
                  int lds, int ldd, long long sS, long long sD)
{
    __shared__ float t[32][33];
    src += (size_t)blockIdx.z * sS;
    dh += (size_t)blockIdx.z * sD;
    dl += (size_t)blockIdx.z * sD;
    int r0 = blockIdx.y * 32, c0 = blockIdx.x * 32;
    int tx = threadIdx.x & 31, ty = threadIdx.x >> 5;   // 32 x 8
#pragma unroll
    for (int i = ty; i < 32; i += 8)
        t[i][tx] = src[(size_t)(r0 + i) * lds + c0 + tx];
    __syncthreads();
#pragma unroll
    for (int j = ty; j < 32; j += 8) {
        if (tx < 16) {
            float a = t[2 * tx][j], b = t[2 * tx + 1][j];
            uint32_t h, l;
            split2(a, b, h, l);
            size_t off = ((size_t)(c0 + j) * ldd + r0) * 2 + tx * 4;
            *(uint32_t*)((char*)dh + off) = h;
            *(uint32_t*)((char*)dl + off) = l;
        }
    }
}

// ---------------------------------------------------------------------------
// Row softmax: reads fp32 scores, writes P hi/lo planes. 1 block / row.
// ---------------------------------------------------------------------------
__global__ __launch_bounds__(256)
void softmax_pl(const float* __restrict__ S,
                __nv_bfloat16* __restrict__ ph, __nv_bfloat16* __restrict__ pl)
{
    __shared__ float red[8];
    int tid = threadIdx.x;
    const float* row = S + (size_t)blockIdx.x * SEQ;

    float4 v0 = *(const float4*)(row + tid * 4);
    float4 v1 = *(const float4*)(row + 1024 + tid * 4);

    float mx = fmaxf(fmaxf(fmaxf(v0.x, v0.y), fmaxf(v0.z, v0.w)),
                     fmaxf(fmaxf(v1.x, v1.y), fmaxf(v1.z, v1.w)));
#pragma unroll
    for (int off = 16; off > 0; off >>= 1)
        mx = fmaxf(mx, __shfl_xor_sync(0xffffffffu, mx, off));
    if ((tid & 31) == 0) red[tid >> 5] = mx;
    __syncthreads();
    if (tid < 32) {
        float t = (tid < 8) ? red[tid] : -1e30f;
#pragma unroll
        for (int off = 4; off > 0; off >>= 1)
            t = fmaxf(t, __shfl_xor_sync(0xffffffffu, t, off));
        if (tid == 0) red[0] = t;
    }
    __syncthreads();
    mx = red[0];

    v0.x = __expf(v0.x - mx); v0.y = __expf(v0.y - mx);
    v0.z = __expf(v0.z - mx); v0.w = __expf(v0.w - mx);
    v1.x = __expf(v1.x - mx); v1.y = __expf(v1.y - mx);
    v1.z = __expf(v1.z - mx); v1.w = __expf(v1.w - mx);

    float sm_ = v0.x + v0.y + v0.z + v0.w + v1.x + v1.y + v1.z + v1.w;
#pragma unroll
    for (int off = 16; off > 0; off >>= 1)
        sm_ += __shfl_xor_sync(0xffffffffu, sm_, off);
    if ((tid & 31) == 0) red[tid >> 5] = sm_;
    __syncthreads();
    if (tid < 32) {
        float t = (tid < 8) ? red[tid] : 0.0f;
#pragma unroll
        for (int off = 4; off > 0; off >>= 1)
            t += __shfl_xor_sync(0xffffffffu, t, off);
        if (tid == 0) red[0] = t;
    }
    __syncthreads();
    float inv = 1.0f / red[0];

    v0.x *= inv; v0.y *= inv; v0.z *= inv; v0.w *= inv;
    v1.x *= inv; v1.y *= inv; v1.z *= inv; v1.w *= inv;

    uint32_t h0, l0, h1, l1;
    uint2* ph2 = (uint2*)(ph + (size_t)blockIdx.x * SEQ);
    uint2* pl2 = (uint2*)(pl + (size_t)blockIdx.x * SEQ);
    split2(v0.x, v0.y, h0, l0);
    split2(v0.z, v0.w, h1, l1);
    ph2[tid] = make_uint2(h0, h1);
    pl2[tid] = make_uint2(l0, l1);
    split2(v1.x, v1.y, h0, l0);
    split2(v1.z, v1.w, h1, l1);
    ph2[256 + tid] = make_uint2(h0, h1);
    pl2[256 + tid] = make_uint2(l0, l1);
}

// ---------------------------------------------------------------------------
extern "C" void kernel_launch(void* const* d_in, const int* in_sizes, int n_in,
                              void* d_out, int out_size)
{
    const float* x     = (const float*)d_in[0];   // [8,2048,768]
    const float* w_qkv = (const float*)d_in[1];   // [768,2304]
    const float* b_qkv = (const float*)d_in[2];   // [2304]
    const float* w_out = (const float*)d_in[3];   // [768,768]
    const float* b_out = (const float*)d_in[4];   // [768]
    float* out = (float*)d_out;                   // [8,2048,768]

    float *sc_p, *v_p;
    __nv_bfloat16 *xh, *xl, *qh, *ql, *kh, *kl, *vth, *vtl, *pph, *ppl,
                  *oh, *ol, *wqh, *wql, *woh, *wol;
    cudaGetSymbolAddress((void**)&sc_p, g_scores);
    cudaGetSymbolAddress((void**)&v_p, g_v);
    cudaGetSymbolAddress((void**)&xh, g_xh);   cudaGetSymbolAddress((void**)&xl, g_xl);
    cudaGetSymbolAddress((void**)&qh, g_qh);   cudaGetSymbolAddress((void**)&ql, g_ql);
    cudaGetSymbolAddress((void**)&kh, g_kh);   cudaGetSymbolAddress((void**)&kl, g_kl);
    cudaGetSymbolAddress((void**)&vth, g_vth); cudaGetSymbolAddress((void**)&vtl, g_vtl);
    cudaGetSymbolAddress((void**)&pph, g_ph);  cudaGetSymbolAddress((void**)&ppl, g_pl);
    cudaGetSymbolAddress((void**)&oh, g_oh);   cudaGetSymbolAddress((void**)&ol, g_ol);
    cudaGetSymbolAddress((void**)&wqh, g_wqh); cudaGetSymbolAddress((void**)&wql, g_wql);
    cudaGetSymbolAddress((void**)&woh, g_woh); cudaGetSymbolAddress((void**)&wol, g_wol);

    cudaFuncSetAttribute(gemm_pl<0>, cudaFuncAttributeMaxDynamicSharedMemorySize, GEMM_SMEM);
    cudaFuncSetAttribute(gemm_pl<1>, cudaFuncAttributeMaxDynamicSharedMemorySize, GEMM_SMEM);
    cudaFuncSetAttribute(gemm_pl<2>, cudaFuncAttributeMaxDynamicSharedMemorySize, GEMM_SMEM);

    const long long sQ  = (long long)SEQ * DIM;     // Q/K plane batch stride
    const long long sS  = (long long)SEQ * SEQ;
    const long long sVT = (long long)DIM * SEQ;

    // 0) pre-split inputs
    convert_pl<<<(BT * DIM / 4 + 255) / 256, 256>>>(x, xh, xl, BT * DIM / 4);
    transpose_pl<<<dim3(QKVO / 32, DIM / 32, 1), 256>>>(w_qkv, wqh, wql, QKVO, DIM, 0, 0);
    transpose_pl<<<dim3(DIM / 32, DIM / 32, 1), 256>>>(w_out, woh, wol, DIM, DIM, 0, 0);

    // 1) QKV projection -> Q/K planes + V fp32
    gemm_pl<2><<<dim3(QKVO / 128, BT / 128, 1), 512, GEMM_SMEM>>>(
        xh, xl, wqh, wql, qh, ql, kh, kl, v_p, b_qkv,
        DIM, DIM, DIM, 0, 1.0f, 0, 0, 0);

    // 1b) V -> vT planes per batch
    transpose_pl<<<dim3(DIM / 32, SEQ / 32, NB), 256>>>(
        v_p, vth, vtl, DIM, SEQ, (long long)SEQ * DIM, sVT);

    // 2) S = 0.125 * Q @ K^T -> fp32 scores
    gemm_pl<0><<<dim3(SEQ / 128, SEQ / 128, NB), 512, GEMM_SMEM>>>(
        qh, ql, kh, kl, sc_p, nullptr, nullptr, nullptr, nullptr, nullptr,
        DIM, DIM, DIM, SEQ, SCALE, sQ, sQ, sS);

    // 3) softmax -> P planes
    softmax_pl<<<NB * SEQ, 256>>>(sc_p, pph, ppl);

    // 4) O = P @ vT^T -> att planes
    gemm_pl<1><<<dim3(DIM / 128, SEQ / 128, NB), 512, GEMM_SMEM>>>(
        pph, ppl, vth, vtl, oh, ol, nullptr, nullptr, nullptr, nullptr,
        SEQ, SEQ, SEQ, DIM, 1.0f, sS, sVT, sQ);

    // 5) out = att @ w_out^T + b_out -> fp32
    gemm_pl<0><<<dim3(DIM / 128, BT / 128, 1), 512, GEMM_SMEM>>>(
        oh, ol, woh, wol, out, nullptr, nullptr, nullptr, nullptr, b_out,
        DIM, DIM, DIM, DIM, 1.0f, 0, 0, 0);
}